// round 6
// baseline (speedup 1.0000x reference)
#include <cuda_runtime.h>
#include <cstddef>

// HelixMemory: output (8, 2558, 2048) f32.
//  rows 510..2557  : copy of memory rows 512..2557 then inputs rows 0..1
//  rows 0..509     : hierarchical pair-averages of memory rows 1024..1535
//
// Per (batch b, column d), src[r] = memory[b][1024+r][d], r in [0,512):
//   L_0[i] = (src[2i]+src[2i+1])/2 ; L_k[i] = (L_{k-1}[2i]+L_{k-1}[2i+1])/2
// Output mapping:
//   L_0[i], i>=128              -> row 126+i                (rows 254..381)
//   L_k[i], k=1..8              -> row 3*2^(8-k)-2 + i
//   L_k[i], k=1..7, i>=2^(7-k)  -> row 2^(8-k)-2 + i-2^(7-k)
//
// R6: copy role unrolled x4 (4 float4 per thread, stride-256 within a
// 1024-f4 block tile = 2 output rows) to raise per-warp MLP; pool role and
// streaming hints unchanged from R5.

#define DCOLS 2048
#define MROWS 2558
#define POOL_BLOCKS 256
#define NTHREADS 256
#define COPY_F4 (8u * 1536u * 512u)   /* 6,291,456 float4 */
#define COPY_BLOCKS 6144u             /* COPY_F4 / (4*256) ; 768 per batch */

__global__ void __launch_bounds__(NTHREADS) helix_fused(
    const float4* __restrict__ mem4,
    const float4* __restrict__ inp4,
    const float*  __restrict__ mem,
    float*        __restrict__ out,
    float4*       __restrict__ out4)
{
    int bx = blockIdx.x;
    if (bx < POOL_BLOCKS) {
        // ---- pooling role (+ copy-through of rows 1024..1535) ----
        __shared__ float l6sm[4][64];
        int b  = bx >> 5;                       // 8 batches
        int dg = bx & 31;                       // 32 column groups of 64
        int s  = threadIdx.x >> 6;              // subtree 0..3 (rows [128s,128s+128))
        int dl = threadIdx.x & 63;
        int d  = dg * 64 + dl;

        const float* src  = mem + ((size_t)b * MROWS + 1024 + 128 * s) * DCOLS + d;
        float*       outb = out + (size_t)b * MROWS * DCOLS + d;
        // copy destination for this thread's first row: out row 1022 + 128*s
        float*       cpy  = outb + (size_t)(1022 + 128 * s) * DCOLS;

        float acc[7];
        #pragma unroll
        for (int l = 0; l < 7; ++l) acc[l] = 0.0f;
        float l6val = 0.0f;

        for (int base = 0; base < 128; base += 8) {
            float v[8];
            #pragma unroll
            for (int j = 0; j < 8; ++j)
                v[j] = __ldcs(src + (size_t)(base + j) * DCOLS);

            #pragma unroll
            for (int j = 0; j < 8; ++j)
                __stcs(cpy + (size_t)(base + j) * DCOLS, v[j]);  // write-through copy

            #pragma unroll
            for (int j = 0; j < 8; ++j) {
                int   r = s * 128 + base + j;   // global row in [0,512)
                float x = v[j];
                #pragma unroll
                for (int l = 0; l < 7; ++l) {
                    acc[l] += x;
                    if (((r + 1) & ((2 << l) - 1)) != 0) break;  // window incomplete
                    x = acc[l] * 0.5f;
                    acc[l] = 0.0f;
                    int i = r >> (l + 1);
                    if (l == 0) {
                        if (i >= 128)
                            __stcs(outb + (size_t)(126 + i) * DCOLS, x);
                    } else {
                        int half = 256 >> l;            // 2^(8-l)
                        __stcs(outb + (size_t)(3 * half - 2 + i) * DCOLS, x);
                        if (i >= (half >> 1))
                            __stcs(outb + (size_t)(half - 2 + i - (half >> 1)) * DCOLS, x);
                    }
                    if (l == 6) l6val = x;              // L_6[s] for this column
                }
            }
        }

        l6sm[s][dl] = l6val;
        __syncthreads();

        if (threadIdx.x < 64) {                 // s == 0 threads finish the column
            float a0 = l6sm[0][dl];
            float a1 = l6sm[1][dl];
            float a2 = l6sm[2][dl];
            float a3 = l6sm[3][dl];
            float l70 = 0.5f * (a0 + a1);       // L_7[0]
            float l71 = 0.5f * (a2 + a3);       // L_7[1]
            __stcs(outb + (size_t)4 * DCOLS, l70);  // part_7 second half
            __stcs(outb + (size_t)5 * DCOLS, l71);
            __stcs(outb, l71);                      // part_8 first half
            __stcs(outb + (size_t)1 * DCOLS, 0.5f * (l70 + l71));   // L_8
        }
    } else {
        // ---- copy role: 4 float4 per thread; skips memory rows 1024..1535 ----
        unsigned blk  = (unsigned)(bx - POOL_BLOCKS);   // 0..6143
        unsigned b    = blk / 768u;                     // batch
        unsigned base = (blk - b * 768u) * 1024u + threadIdx.x;  // f4 index in batch tile

        const float4* msrc = mem4 + (size_t)b * (MROWS * 512);
        const float4* isrc = inp4 + (size_t)b * (1024 * 512);
        float4*       dst  = out4 + (size_t)b * (MROWS * 512);

        float4 v[4];
        unsigned srow[4], c4[4];
        #pragma unroll
        for (int j = 0; j < 4; ++j) {
            unsigned idx  = base + j * 256u;   // < 786432
            unsigned ridx = idx >> 9;          // 0..1535
            c4[j]   = idx & 511u;
            // ridx 0..511 -> srow 512..1023 ; ridx 512..1535 -> srow 1536..2559
            srow[j] = (ridx < 512u) ? (512u + ridx) : (1024u + ridx);
            v[j] = (srow[j] < (unsigned)MROWS)
                 ? __ldcs(msrc + (size_t)srow[j] * 512 + c4[j])
                 : __ldcs(isrc + (size_t)(srow[j] - MROWS) * 512 + c4[j]);
        }
        #pragma unroll
        for (int j = 0; j < 4; ++j)
            __stcs(dst + (size_t)(srow[j] - 2) * 512 + c4[j], v[j]);
    }
}

extern "C" void kernel_launch(void* const* d_in, const int* in_sizes, int n_in,
                              void* d_out, int out_size)
{
    // Identify tensors by element count (inputs: 8*1024*2048; memory: 8*2558*2048).
    const float* inputs = (const float*)d_in[0];
    const float* memory = (const float*)d_in[1];
    if (n_in >= 2 && in_sizes[0] > in_sizes[1]) {
        memory = (const float*)d_in[0];
        inputs = (const float*)d_in[1];
    }
    float* out = (float*)d_out;

    helix_fused<<<POOL_BLOCKS + COPY_BLOCKS, NTHREADS>>>(
        (const float4*)memory, (const float4*)inputs, memory, out, (float4*)out);
}

// round 7
// speedup vs baseline: 1.0193x; 1.0193x over previous
#include <cuda_runtime.h>
#include <cstddef>

// HelixMemory: output (8, 2558, 2048) f32.
//  rows 510..2557  : copy of memory rows 512..2557 then inputs rows 0..1
//  rows 0..509     : hierarchical pair-averages of memory rows 1024..1535
//
// Per (batch b, column d), src[r] = memory[b][1024+r][d], r in [0,512):
//   L_0[i] = (src[2i]+src[2i+1])/2 ; L_k[i] = (L_{k-1}[2i]+L_{k-1}[2i+1])/2
// Output mapping:
//   L_0[i], i>=128              -> row 126+i                (rows 254..381)
//   L_k[i], k=1..8              -> row 3*2^(8-k)-2 + i
//   L_k[i], k=1..7, i>=2^(7-k)  -> row 2^(8-k)-2 + i-2^(7-k)
//
// R7: R5 structure (best) with copy role at MLP=2: each thread handles f4
// indices t and t + COPY_F4/2 as two independent streams. Pool role identical
// to R5. Streaming hints everywhere (read-once/write-once traffic).

#define DCOLS 2048
#define MROWS 2558
#define POOL_BLOCKS 256
#define NTHREADS 256
#define COPY_F4 (8u * 1536u * 512u)   /* 6,291,456 float4 */
#define COPY_HALF (COPY_F4 / 2u)      /* 3,145,728 */
#define COPY_BLOCKS (COPY_HALF / NTHREADS) /* 12288 */

__global__ void __launch_bounds__(NTHREADS) helix_fused(
    const float4* __restrict__ mem4,
    const float4* __restrict__ inp4,
    const float*  __restrict__ mem,
    float*        __restrict__ out,
    float4*       __restrict__ out4)
{
    int bx = blockIdx.x;
    if (bx < POOL_BLOCKS) {
        // ---- pooling role (+ copy-through of rows 1024..1535) ----
        __shared__ float l6sm[4][64];
        int b  = bx >> 5;                       // 8 batches
        int dg = bx & 31;                       // 32 column groups of 64
        int s  = threadIdx.x >> 6;              // subtree 0..3 (rows [128s,128s+128))
        int dl = threadIdx.x & 63;
        int d  = dg * 64 + dl;

        const float* src  = mem + ((size_t)b * MROWS + 1024 + 128 * s) * DCOLS + d;
        float*       outb = out + (size_t)b * MROWS * DCOLS + d;
        // copy destination for this thread's first row: out row 1022 + 128*s
        float*       cpy  = outb + (size_t)(1022 + 128 * s) * DCOLS;

        float acc[7];
        #pragma unroll
        for (int l = 0; l < 7; ++l) acc[l] = 0.0f;
        float l6val = 0.0f;

        for (int base = 0; base < 128; base += 8) {
            float v[8];
            #pragma unroll
            for (int j = 0; j < 8; ++j)
                v[j] = __ldcs(src + (size_t)(base + j) * DCOLS);

            #pragma unroll
            for (int j = 0; j < 8; ++j)
                __stcs(cpy + (size_t)(base + j) * DCOLS, v[j]);  // write-through copy

            #pragma unroll
            for (int j = 0; j < 8; ++j) {
                int   r = s * 128 + base + j;   // global row in [0,512)
                float x = v[j];
                #pragma unroll
                for (int l = 0; l < 7; ++l) {
                    acc[l] += x;
                    if (((r + 1) & ((2 << l) - 1)) != 0) break;  // window incomplete
                    x = acc[l] * 0.5f;
                    acc[l] = 0.0f;
                    int i = r >> (l + 1);
                    if (l == 0) {
                        if (i >= 128)
                            __stcs(outb + (size_t)(126 + i) * DCOLS, x);
                    } else {
                        int half = 256 >> l;            // 2^(8-l)
                        __stcs(outb + (size_t)(3 * half - 2 + i) * DCOLS, x);
                        if (i >= (half >> 1))
                            __stcs(outb + (size_t)(half - 2 + i - (half >> 1)) * DCOLS, x);
                    }
                    if (l == 6) l6val = x;              // L_6[s] for this column
                }
            }
        }

        l6sm[s][dl] = l6val;
        __syncthreads();

        if (threadIdx.x < 64) {                 // s == 0 threads finish the column
            float a0 = l6sm[0][dl];
            float a1 = l6sm[1][dl];
            float a2 = l6sm[2][dl];
            float a3 = l6sm[3][dl];
            float l70 = 0.5f * (a0 + a1);       // L_7[0]
            float l71 = 0.5f * (a2 + a3);       // L_7[1]
            __stcs(outb + (size_t)4 * DCOLS, l70);  // part_7 second half
            __stcs(outb + (size_t)5 * DCOLS, l71);
            __stcs(outb, l71);                      // part_8 first half
            __stcs(outb + (size_t)1 * DCOLS, 0.5f * (l70 + l71));   // L_8
        }
    } else {
        // ---- copy role: 2 independent float4 streams per thread ----
        unsigned t0 = (unsigned)(bx - POOL_BLOCKS) * NTHREADS + threadIdx.x;

        float4 v[2];
        unsigned b[2], srow[2], c4[2];
        #pragma unroll
        for (int j = 0; j < 2; ++j) {
            unsigned t    = t0 + (unsigned)j * COPY_HALF;
            b[j]          = t / (1536u * 512u);
            unsigned rem  = t - b[j] * (1536u * 512u);
            unsigned ridx = rem >> 9;            // 0..1535
            c4[j]         = rem & 511u;
            // ridx 0..511 -> srow 512..1023 ; ridx 512..1535 -> srow 1536..2559
            srow[j] = (ridx < 512u) ? (512u + ridx) : (1024u + ridx);
            v[j] = (srow[j] < (unsigned)MROWS)
                 ? __ldcs(mem4 + (size_t)b[j] * (MROWS * 512) + (size_t)srow[j] * 512 + c4[j])
                 : __ldcs(inp4 + (size_t)b[j] * (1024 * 512) + (size_t)(srow[j] - MROWS) * 512 + c4[j]);
        }
        #pragma unroll
        for (int j = 0; j < 2; ++j)
            __stcs(out4 + (size_t)b[j] * (MROWS * 512) + (size_t)(srow[j] - 2) * 512 + c4[j], v[j]);
    }
}

extern "C" void kernel_launch(void* const* d_in, const int* in_sizes, int n_in,
                              void* d_out, int out_size)
{
    // Identify tensors by element count (inputs: 8*1024*2048; memory: 8*2558*2048).
    const float* inputs = (const float*)d_in[0];
    const float* memory = (const float*)d_in[1];
    if (n_in >= 2 && in_sizes[0] > in_sizes[1]) {
        memory = (const float*)d_in[0];
        inputs = (const float*)d_in[1];
    }
    float* out = (float*)d_out;

    helix_fused<<<POOL_BLOCKS + COPY_BLOCKS, NTHREADS>>>(
        (const float4*)memory, (const float4*)inputs, memory, out, (float4*)out);
}

// round 8
// speedup vs baseline: 1.0876x; 1.0670x over previous
#include <cuda_runtime.h>
#include <cstddef>

// HelixMemory: output (8, 2558, 2048) f32.
//  rows 510..2557  : copy of memory rows 512..2557 then inputs rows 0..1
//  rows 0..509     : hierarchical pair-averages of memory rows 1024..1535
//
// Per (batch b, column d), src[r] = memory[b][1024+r][d], r in [0,512):
//   L_0[i] = (src[2i]+src[2i+1])/2 ; L_k[i] = (L_{k-1}[2i]+L_{k-1}[2i+1])/2
// Output mapping:
//   L_0[i], i>=128              -> row 126+i                (rows 254..381)
//   L_k[i], k=1..8              -> row 3*2^(8-k)-2 + i
//   L_k[i], k=1..7, i>=2^(7-k)  -> row 2^(8-k)-2 + i-2^(7-k)
//
// R8: exact R5 structure (best: copy role = 1 float4/thread, 24576 copy
// blocks; pool role with write-through + in-block L7/L8). Single change:
// copy-role stores use __stwt (write-through, no L2 allocation) so the 150MB
// write-once stream doesn't consume L2 state needed by the read stream.

#define DCOLS 2048
#define MROWS 2558
#define POOL_BLOCKS 256
#define NTHREADS 256
#define COPY_F4 (8u * 1536u * 512u) /* 6,291,456 float4 */

__global__ void __launch_bounds__(NTHREADS) helix_fused(
    const float4* __restrict__ mem4,
    const float4* __restrict__ inp4,
    const float*  __restrict__ mem,
    float*        __restrict__ out,
    float4*       __restrict__ out4)
{
    int bx = blockIdx.x;
    if (bx < POOL_BLOCKS) {
        // ---- pooling role (+ copy-through of rows 1024..1535) ----
        __shared__ float l6sm[4][64];
        int b  = bx >> 5;                       // 8 batches
        int dg = bx & 31;                       // 32 column groups of 64
        int s  = threadIdx.x >> 6;              // subtree 0..3 (rows [128s,128s+128))
        int dl = threadIdx.x & 63;
        int d  = dg * 64 + dl;

        const float* src  = mem + ((size_t)b * MROWS + 1024 + 128 * s) * DCOLS + d;
        float*       outb = out + (size_t)b * MROWS * DCOLS + d;
        // copy destination for this thread's first row: out row 1022 + 128*s
        float*       cpy  = outb + (size_t)(1022 + 128 * s) * DCOLS;

        float acc[7];
        #pragma unroll
        for (int l = 0; l < 7; ++l) acc[l] = 0.0f;
        float l6val = 0.0f;

        for (int base = 0; base < 128; base += 8) {
            float v[8];
            #pragma unroll
            for (int j = 0; j < 8; ++j)
                v[j] = __ldcs(src + (size_t)(base + j) * DCOLS);

            #pragma unroll
            for (int j = 0; j < 8; ++j)
                __stcs(cpy + (size_t)(base + j) * DCOLS, v[j]);  // write-through copy

            #pragma unroll
            for (int j = 0; j < 8; ++j) {
                int   r = s * 128 + base + j;   // global row in [0,512)
                float x = v[j];
                #pragma unroll
                for (int l = 0; l < 7; ++l) {
                    acc[l] += x;
                    if (((r + 1) & ((2 << l) - 1)) != 0) break;  // window incomplete
                    x = acc[l] * 0.5f;
                    acc[l] = 0.0f;
                    int i = r >> (l + 1);
                    if (l == 0) {
                        if (i >= 128)
                            __stcs(outb + (size_t)(126 + i) * DCOLS, x);
                    } else {
                        int half = 256 >> l;            // 2^(8-l)
                        __stcs(outb + (size_t)(3 * half - 2 + i) * DCOLS, x);
                        if (i >= (half >> 1))
                            __stcs(outb + (size_t)(half - 2 + i - (half >> 1)) * DCOLS, x);
                    }
                    if (l == 6) l6val = x;              // L_6[s] for this column
                }
            }
        }

        l6sm[s][dl] = l6val;
        __syncthreads();

        if (threadIdx.x < 64) {                 // s == 0 threads finish the column
            float a0 = l6sm[0][dl];
            float a1 = l6sm[1][dl];
            float a2 = l6sm[2][dl];
            float a3 = l6sm[3][dl];
            float l70 = 0.5f * (a0 + a1);       // L_7[0]
            float l71 = 0.5f * (a2 + a3);       // L_7[1]
            __stcs(outb + (size_t)4 * DCOLS, l70);  // part_7 second half
            __stcs(outb + (size_t)5 * DCOLS, l71);
            __stcs(outb, l71);                      // part_8 first half
            __stcs(outb + (size_t)1 * DCOLS, 0.5f * (l70 + l71));   // L_8
        }
    } else {
        // ---- copy role: one float4 per thread; skips memory rows 1024..1535 ----
        unsigned t = (unsigned)(bx - POOL_BLOCKS) * NTHREADS + threadIdx.x;
        if (t >= COPY_F4) return;
        unsigned b    = t / (1536u * 512u);
        unsigned rem  = t - b * (1536u * 512u);
        unsigned ridx = rem >> 9;                // 0..1535
        unsigned c4   = rem & 511u;
        // ridx 0..511 -> srow 512..1023 ; ridx 512..1535 -> srow 1536..2559
        unsigned srow = (ridx < 512u) ? (512u + ridx) : (1024u + ridx);
        float4 v;
        if (srow < (unsigned)MROWS)
            v = __ldcs(mem4 + (size_t)b * (MROWS * 512) + (size_t)srow * 512 + c4);
        else
            v = __ldcs(inp4 + (size_t)b * (1024 * 512) + (size_t)(srow - MROWS) * 512 + c4);
        __stwt(out4 + (size_t)b * (MROWS * 512) + (size_t)(srow - 2) * 512 + c4, v);
    }
}

extern "C" void kernel_launch(void* const* d_in, const int* in_sizes, int n_in,
                              void* d_out, int out_size)
{
    // Identify tensors by element count (inputs: 8*1024*2048; memory: 8*2558*2048).
    const float* inputs = (const float*)d_in[0];
    const float* memory = (const float*)d_in[1];
    if (n_in >= 2 && in_sizes[0] > in_sizes[1]) {
        memory = (const float*)d_in[0];
        inputs = (const float*)d_in[1];
    }
    float* out = (float*)d_out;

    unsigned copy_blocks = (COPY_F4 + NTHREADS - 1) / NTHREADS;  // 24576
    helix_fused<<<POOL_BLOCKS + copy_blocks, NTHREADS>>>(
        (const float4*)memory, (const float4*)inputs, memory, out, (float4*)out);
}